// round 6
// baseline (speedup 1.0000x reference)
#include <cuda_runtime.h>
#include <cuda_bf16.h>
#include <stdint.h>

#define Hdim 2048
#define HH   (Hdim * Hdim)        // 4194304
#define NIDX 2000000
#define NB   256
#define CNT_SHIFT 24              // bits 24..31 of bin words hold the per-pixel sample count

// ---------------- device scratch (no allocations allowed) ----------------
__device__ unsigned int  g_hist[6 * NB];      // [0..2]=dst(ref_masked), [3..5]=ref(target_masked)
__device__ unsigned int  g_bin_ref[HH];       // bits0-23: packed 3-ch bins of ref_masked; bits24+: count
__device__ unsigned int  g_bin_tgt[HH];       // bits0-23: packed 3-ch bins of tgt_masked; bits24+: count
__device__ float         g_table[3 * NB];
__device__ double        g_acc;
__device__ unsigned int  g_done_hist;         // ticket for fused tables (zero-init)
__device__ unsigned int  g_done_loss;         // ticket for fused finalize (zero-init)

// ---------------- helpers ----------------
__device__ __forceinline__ float dn255(float x) {
    float v = (x + 1.0f) * 0.5f;
    v = fminf(fmaxf(v, 0.0f), 1.0f);
    return v * 255.0f;
}
__device__ __forceinline__ unsigned int binof(float v) {
    int b = (int)v;                  // v >= 0, trunc == floor
    b = b < 0 ? 0 : b;
    return (unsigned int)(b > 255 ? 255 : b);
}
__device__ __forceinline__ float warpReduceSumF(float v) {
    #pragma unroll
    for (int o = 16; o > 0; o >>= 1) v += __shfl_down_sync(0xffffffffu, v, o);
    return v;
}
__device__ __forceinline__ unsigned int warpReduceSumU(unsigned int v) {
    #pragma unroll
    for (int o = 16; o > 0; o >>= 1) v += __shfl_down_sync(0xffffffffu, v, o);
    return v;
}

// ---------------- K1: packed per-pixel bins (coalesced; full-word store resets counts) ----------------
__global__ void __launch_bounds__(256) k_binify(
    const float* __restrict__ ref, const float* __restrict__ tgt,
    const float* __restrict__ msrc, const float* __restrict__ mtar)
{
    if (blockIdx.x == 0) {   // fold tiny init (hist consumed only in k_hist)
        for (int i = threadIdx.x; i < 6 * NB; i += blockDim.x) g_hist[i] = 0u;
        if (threadIdx.x == 0) g_acc = 0.0;
    }

    const int NP4 = HH / 4;
    int idx = blockIdx.x * blockDim.x + threadIdx.x;    // exactly NP4 threads launched
    if (idx >= NP4) return;

    const float4* m4  = reinterpret_cast<const float4*>(msrc);
    const float4* mt4 = reinterpret_cast<const float4*>(mtar);
    const float4* rf4 = reinterpret_cast<const float4*>(ref);
    const float4* tg4 = reinterpret_cast<const float4*>(tgt);

    float4 ms = m4[idx];
    float4 mt = mt4[idx];
    float msA[4] = {ms.x, ms.y, ms.z, ms.w};
    float mtA[4] = {mt.x, mt.y, mt.z, mt.w};

    unsigned int pr[4] = {0u, 0u, 0u, 0u};
    unsigned int pt[4] = {0u, 0u, 0u, 0u};
    #pragma unroll
    for (int c = 0; c < 3; c++) {
        float4 rv = rf4[c * NP4 + idx];
        float4 tv = tg4[c * NP4 + idx];
        float rvA[4] = {rv.x, rv.y, rv.z, rv.w};
        float tvA[4] = {tv.x, tv.y, tv.z, tv.w};
        #pragma unroll
        for (int l = 0; l < 4; l++) {
            pr[l] |= binof(dn255(rvA[l]) * msA[l]) << (8 * c);
            pt[l] |= binof(dn255(tvA[l]) * mtA[l]) << (8 * c);
        }
    }
    reinterpret_cast<uint4*>(g_bin_ref)[idx] = make_uint4(pr[0], pr[1], pr[2], pr[3]);
    reinterpret_cast<uint4*>(g_bin_tgt)[idx] = make_uint4(pt[0], pt[1], pt[2], pt[3]);
}

// ---------------- K2: pure count scatter (no-return REDs only) ----------------
#define SPT 8   // samples per thread
__global__ void __launch_bounds__(256) k_sample(
    const int* __restrict__ i0, const int* __restrict__ i1,
    const int* __restrict__ i2, const int* __restrict__ i3)
{
    int t = blockIdx.x * blockDim.x + threadIdx.x;
    int k = t * SPT;
    const unsigned int one = 1u << CNT_SHIFT;
    if (k + SPT - 1 < NIDX) {
        #pragma unroll
        for (int u = 0; u < SPT; u += 4) {
            int4 a0 = *reinterpret_cast<const int4*>(i0 + k + u);
            int4 a1 = *reinterpret_cast<const int4*>(i1 + k + u);
            int4 a2 = *reinterpret_cast<const int4*>(i2 + k + u);
            int4 a3 = *reinterpret_cast<const int4*>(i3 + k + u);
            atomicAdd(&g_bin_ref[a0.x * Hdim + a1.x], one);
            atomicAdd(&g_bin_ref[a0.y * Hdim + a1.y], one);
            atomicAdd(&g_bin_ref[a0.z * Hdim + a1.z], one);
            atomicAdd(&g_bin_ref[a0.w * Hdim + a1.w], one);
            atomicAdd(&g_bin_tgt[a2.x * Hdim + a3.x], one);
            atomicAdd(&g_bin_tgt[a2.y * Hdim + a3.y], one);
            atomicAdd(&g_bin_tgt[a2.z * Hdim + a3.z], one);
            atomicAdd(&g_bin_tgt[a2.w * Hdim + a3.w], one);
        }
    } else {
        for (; k < NIDX; k++) {
            atomicAdd(&g_bin_ref[i0[k] * Hdim + i1[k]], one);
            atomicAdd(&g_bin_tgt[i2[k] * Hdim + i3[k]], one);
        }
    }
}

// ---------------- K3: weighted histogram (coalesced stream) + fused tables in last block ----------------
__global__ void __launch_bounds__(256) k_hist()
{
    unsigned int c0[6]   = {0, 0, 0, 0, 0, 0};
    unsigned int c255[6] = {0, 0, 0, 0, 0, 0};

    const int NP4 = HH / 4;
    const uint4* br4 = reinterpret_cast<const uint4*>(g_bin_ref);
    const uint4* bt4 = reinterpret_cast<const uint4*>(g_bin_tgt);
    int stride = gridDim.x * blockDim.x;

    for (int idx = blockIdx.x * blockDim.x + threadIdx.x; idx < NP4; idx += stride) {
        uint4 wr = br4[idx];
        uint4 wt = bt4[idx];
        unsigned int wrA[4] = {wr.x, wr.y, wr.z, wr.w};
        unsigned int wtA[4] = {wt.x, wt.y, wt.z, wt.w};
        #pragma unroll
        for (int l = 0; l < 4; l++) {
            unsigned int cnt = wrA[l] >> CNT_SHIFT;
            if (cnt) {
                #pragma unroll
                for (int c = 0; c < 3; c++) {
                    unsigned int b = (wrA[l] >> (8 * c)) & 255u;
                    c0[c]   += (b == 0u)   ? cnt : 0u;
                    c255[c] += (b == 255u) ? cnt : 0u;
                    if (b - 1u < 254u) atomicAdd(&g_hist[c * NB + b], cnt);
                }
            }
            unsigned int cnt2 = wtA[l] >> CNT_SHIFT;
            if (cnt2) {
                #pragma unroll
                for (int c = 0; c < 3; c++) {
                    unsigned int b = (wtA[l] >> (8 * c)) & 255u;
                    c0[3 + c]   += (b == 0u)   ? cnt2 : 0u;
                    c255[3 + c] += (b == 255u) ? cnt2 : 0u;
                    if (b - 1u < 254u) atomicAdd(&g_hist[(3 + c) * NB + b], cnt2);
                }
            }
        }
    }

    // flush register counters: warp reduce, lane0 RED
    int lane = threadIdx.x & 31;
    #pragma unroll
    for (int h = 0; h < 6; h++) {
        unsigned int v0 = warpReduceSumU(c0[h]);
        unsigned int v1 = warpReduceSumU(c255[h]);
        if (lane == 0) {
            if (v0) atomicAdd(&g_hist[h * NB + 0],   v0);
            if (v1) atomicAdd(&g_hist[h * NB + 255], v1);
        }
    }

    // ---- last-block fused tables ----
    __shared__ bool s_last;
    __threadfence();
    if (threadIdx.x == 0) {
        unsigned int ticket = atomicAdd(&g_done_hist, 1u);
        s_last = (ticket == gridDim.x - 1);
        if (s_last) g_done_hist = 0u;   // reset for next replay
    }
    __syncthreads();
    if (!s_last) return;

    __shared__ unsigned int s0[NB], s1[NB];
    __shared__ float r[3][NB];   // cdf_dst
    __shared__ float a[3][NB];   // cdf_ref
    int i = threadIdx.x;

    for (int h = 0; h < 6; h++) {
        s0[i] = g_hist[h * NB + i];
        __syncthreads();
        unsigned int* src = s0; unsigned int* dst = s1;
        #pragma unroll
        for (int off = 1; off < NB; off <<= 1) {   // Hillis-Steele, exact integer adds
            unsigned int v = src[i];
            if (i >= off) v += src[i - off];
            dst[i] = v;
            __syncthreads();
            unsigned int* tmpp = src; src = dst; dst = tmpp;
        }
        float tot = (float)src[NB - 1];
        float v = (float)src[i] / tot;             // matches jnp: exact int in f32, then divide
        if (h < 3) r[h][i] = v; else a[h - 3][i] = v;
        __syncthreads();
    }

    #pragma unroll
    for (int c = 0; c < 3; c++) {
        float tbl;
        if (i == 0)           tbl = 0.0f;
        else if (i == NB - 1) tbl = 255.0f;
        else {
            float ri = r[c][i];
            int j = -1;
            for (int jj = 1; jj < NB; jj++) {
                if (ri >= a[c][jj - 1] && ri <= a[c][jj]) { j = jj; break; }
            }
            tbl = (j >= 0) ? (float)j : (float)i;
        }
        g_table[c * NB + i] = tbl;
    }
}

// ---------------- K4: loss over all pixels (pure-read stream) + fused finalize ----------------
__global__ void __launch_bounds__(256) k_loss(
    const float* __restrict__ inp, const float* __restrict__ ref,
    const float* __restrict__ msrc, float* __restrict__ out)
{
    __shared__ float stab[3 * NB];
    for (int i = threadIdx.x; i < 3 * NB; i += blockDim.x) stab[i] = g_table[i];
    __syncthreads();

    const float4* m4  = reinterpret_cast<const float4*>(msrc);
    const float4* in4 = reinterpret_cast<const float4*>(inp);
    const float4* rf4 = reinterpret_cast<const float4*>(ref);
    const uint4*  b4  = reinterpret_cast<const uint4*>(g_bin_ref);

    float acc = 0.0f;
    int stride = gridDim.x * blockDim.x;
    const int NP4 = HH / 4;
    for (int idx = blockIdx.x * blockDim.x + threadIdx.x; idx < NP4; idx += stride) {
        float4 ms = m4[idx];
        uint4  bw = b4[idx];
        float msA[4] = {ms.x, ms.y, ms.z, ms.w};
        unsigned int wA[4] = {bw.x, bw.y, bw.z, bw.w};
        #pragma unroll
        for (int c = 0; c < 3; c++) {
            float4 iv = in4[c * NP4 + idx];
            float4 rv = rf4[c * NP4 + idx];
            float ivA[4] = {iv.x, iv.y, iv.z, iv.w};
            float rvA[4] = {rv.x, rv.y, rv.z, rv.w};
            #pragma unroll
            for (int l = 0; l < 4; l++) {
                float im = dn255(ivA[l]) * msA[l];
                float rm = dn255(rvA[l]) * msA[l];
                float match = (wA[l] >> CNT_SHIFT)
                            ? stab[c * NB + (int)((wA[l] >> (8 * c)) & 255u)]
                            : rm;
                acc += fabsf(im - match);
            }
        }
    }

    // block reduce -> double atomic; last block finalizes
    float s = warpReduceSumF(acc);
    __shared__ float ws[32];
    int lane = threadIdx.x & 31, w = threadIdx.x >> 5;
    if (lane == 0) ws[w] = s;
    __syncthreads();
    if (w == 0) {
        float v = (lane < (int)(blockDim.x >> 5)) ? ws[lane] : 0.0f;
        v = warpReduceSumF(v);
        if (lane == 0) {
            atomicAdd(&g_acc, (double)v);
            __threadfence();
            unsigned int ticket = atomicAdd(&g_done_loss, 1u);
            if (ticket == gridDim.x - 1) {
                out[0] = (float)(g_acc / (double)(3.0 * (double)HH));
                g_done_loss = 0u;   // reset for next replay
            }
        }
    }
}

// ---------------- launch ----------------
extern "C" void kernel_launch(void* const* d_in, const int* in_sizes, int n_in,
                              void* d_out, int out_size)
{
    const float* input_data  = (const float*)d_in[0];
    const float* target_data = (const float*)d_in[1];
    const float* ref         = (const float*)d_in[2];
    const float* mask_src    = (const float*)d_in[3];
    const float* mask_tar    = (const float*)d_in[4];
    const int* idx0 = (const int*)d_in[5];
    const int* idx1 = (const int*)d_in[6];
    const int* idx2 = (const int*)d_in[7];
    const int* idx3 = (const int*)d_in[8];
    float* out = (float*)d_out;

    k_binify<<<HH / 4 / 256, 256>>>(ref, target_data, mask_src, mask_tar);
    k_sample<<<(NIDX / SPT + 255) / 256, 256>>>(idx0, idx1, idx2, idx3);
    k_hist<<<512, 256>>>();
    k_loss<<<2048, 256>>>(input_data, ref, mask_src, out);
}

// round 8
// speedup vs baseline: 1.9280x; 1.9280x over previous
#include <cuda_runtime.h>
#include <cuda_bf16.h>
#include <stdint.h>

#define Hdim 2048
#define HH   (Hdim * Hdim)        // 4194304
#define NIDX 2000000
#define NB   256
#define CNT_SHIFT 24              // bits 24..31 of bin words hold the per-pixel sample count

// ---------------- device scratch (no allocations allowed) ----------------
__device__ unsigned int  g_hist[6 * NB];      // [0..2]=dst(ref_masked), [3..5]=ref(target_masked)
__device__ unsigned int  g_bin_ref[HH];       // bits0-23: packed 3-ch bins of ref_masked; bits24+: count
__device__ unsigned int  g_bin_tgt[HH];       // bits0-23: packed 3-ch bins of tgt_masked; bits24+: count
__device__ float         g_table[3 * NB];
__device__ double        g_acc;
__device__ unsigned int  g_done_hist;         // ticket for fused tables (zero-init)
__device__ unsigned int  g_done_loss;         // ticket for fused finalize (zero-init)

// ---------------- helpers ----------------
__device__ __forceinline__ float dn255(float x) {
    float v = (x + 1.0f) * 0.5f;
    v = fminf(fmaxf(v, 0.0f), 1.0f);
    return v * 255.0f;
}
__device__ __forceinline__ unsigned int binof(float v) {
    int b = (int)v;                  // v >= 0, trunc == floor
    b = b < 0 ? 0 : b;
    return (unsigned int)(b > 255 ? 255 : b);
}
__device__ __forceinline__ float warpReduceSumF(float v) {
    #pragma unroll
    for (int o = 16; o > 0; o >>= 1) v += __shfl_down_sync(0xffffffffu, v, o);
    return v;
}
__device__ __forceinline__ unsigned int warpReduceSumU(unsigned int v) {
    #pragma unroll
    for (int o = 16; o > 0; o >>= 1) v += __shfl_down_sync(0xffffffffu, v, o);
    return v;
}

// ---------------- K1: packed per-pixel bins (coalesced; full-word store resets counts) ----------------
__global__ void __launch_bounds__(256) k_binify(
    const float* __restrict__ ref, const float* __restrict__ tgt,
    const float* __restrict__ msrc, const float* __restrict__ mtar)
{
    if (blockIdx.x == 0) {   // fold tiny init (hist consumed only in k_hist)
        for (int i = threadIdx.x; i < 6 * NB; i += blockDim.x) g_hist[i] = 0u;
        if (threadIdx.x == 0) g_acc = 0.0;
    }

    const int NP4 = HH / 4;
    int idx = blockIdx.x * blockDim.x + threadIdx.x;    // exactly NP4 threads launched
    if (idx >= NP4) return;

    const float4* m4  = reinterpret_cast<const float4*>(msrc);
    const float4* mt4 = reinterpret_cast<const float4*>(mtar);
    const float4* rf4 = reinterpret_cast<const float4*>(ref);
    const float4* tg4 = reinterpret_cast<const float4*>(tgt);

    float4 ms = m4[idx];
    float4 mt = mt4[idx];
    float msA[4] = {ms.x, ms.y, ms.z, ms.w};
    float mtA[4] = {mt.x, mt.y, mt.z, mt.w};

    unsigned int pr[4] = {0u, 0u, 0u, 0u};
    unsigned int pt[4] = {0u, 0u, 0u, 0u};
    #pragma unroll
    for (int c = 0; c < 3; c++) {
        float4 rv = rf4[c * NP4 + idx];
        float4 tv = tg4[c * NP4 + idx];
        float rvA[4] = {rv.x, rv.y, rv.z, rv.w};
        float tvA[4] = {tv.x, tv.y, tv.z, tv.w};
        #pragma unroll
        for (int l = 0; l < 4; l++) {
            pr[l] |= binof(dn255(rvA[l]) * msA[l]) << (8 * c);
            pt[l] |= binof(dn255(tvA[l]) * mtA[l]) << (8 * c);
        }
    }
    reinterpret_cast<uint4*>(g_bin_ref)[idx] = make_uint4(pr[0], pr[1], pr[2], pr[3]);
    reinterpret_cast<uint4*>(g_bin_tgt)[idx] = make_uint4(pt[0], pt[1], pt[2], pt[3]);
}

// ---------------- K2: pure count scatter (no-return REDs only) ----------------
#define SPT 8   // samples per thread
__global__ void __launch_bounds__(256) k_sample(
    const int* __restrict__ i0, const int* __restrict__ i1,
    const int* __restrict__ i2, const int* __restrict__ i3)
{
    int t = blockIdx.x * blockDim.x + threadIdx.x;
    int k = t * SPT;
    const unsigned int one = 1u << CNT_SHIFT;
    if (k + SPT - 1 < NIDX) {
        #pragma unroll
        for (int u = 0; u < SPT; u += 4) {
            int4 a0 = *reinterpret_cast<const int4*>(i0 + k + u);
            int4 a1 = *reinterpret_cast<const int4*>(i1 + k + u);
            int4 a2 = *reinterpret_cast<const int4*>(i2 + k + u);
            int4 a3 = *reinterpret_cast<const int4*>(i3 + k + u);
            atomicAdd(&g_bin_ref[a0.x * Hdim + a1.x], one);
            atomicAdd(&g_bin_ref[a0.y * Hdim + a1.y], one);
            atomicAdd(&g_bin_ref[a0.z * Hdim + a1.z], one);
            atomicAdd(&g_bin_ref[a0.w * Hdim + a1.w], one);
            atomicAdd(&g_bin_tgt[a2.x * Hdim + a3.x], one);
            atomicAdd(&g_bin_tgt[a2.y * Hdim + a3.y], one);
            atomicAdd(&g_bin_tgt[a2.z * Hdim + a3.z], one);
            atomicAdd(&g_bin_tgt[a2.w * Hdim + a3.w], one);
        }
    } else {
        for (; k < NIDX; k++) {
            atomicAdd(&g_bin_ref[i0[k] * Hdim + i1[k]], one);
            atomicAdd(&g_bin_tgt[i2[k] * Hdim + i3[k]], one);
        }
    }
}

// ---------------- K3: weighted histogram (shared-privatized) + fused tables in last block ----------------
__global__ void __launch_bounds__(256) k_hist()
{
    __shared__ unsigned int sh[6 * NB];
    for (int i = threadIdx.x; i < 6 * NB; i += blockDim.x) sh[i] = 0u;
    __syncthreads();

    unsigned int c0[6]   = {0, 0, 0, 0, 0, 0};
    unsigned int c255[6] = {0, 0, 0, 0, 0, 0};

    const int NP4 = HH / 4;
    const uint4* br4 = reinterpret_cast<const uint4*>(g_bin_ref);
    const uint4* bt4 = reinterpret_cast<const uint4*>(g_bin_tgt);
    int stride = gridDim.x * blockDim.x;

    for (int idx = blockIdx.x * blockDim.x + threadIdx.x; idx < NP4; idx += stride) {
        uint4 wr = br4[idx];
        uint4 wt = bt4[idx];
        unsigned int wrA[4] = {wr.x, wr.y, wr.z, wr.w};
        unsigned int wtA[4] = {wt.x, wt.y, wt.z, wt.w};
        #pragma unroll
        for (int l = 0; l < 4; l++) {
            unsigned int cnt = wrA[l] >> CNT_SHIFT;
            if (cnt) {
                #pragma unroll
                for (int c = 0; c < 3; c++) {
                    unsigned int b = (wrA[l] >> (8 * c)) & 255u;
                    c0[c]   += (b == 0u)   ? cnt : 0u;
                    c255[c] += (b == 255u) ? cnt : 0u;
                    if (b - 1u < 254u) atomicAdd(&sh[c * NB + b], cnt);
                }
            }
            unsigned int cnt2 = wtA[l] >> CNT_SHIFT;
            if (cnt2) {
                #pragma unroll
                for (int c = 0; c < 3; c++) {
                    unsigned int b = (wtA[l] >> (8 * c)) & 255u;
                    c0[3 + c]   += (b == 0u)   ? cnt2 : 0u;
                    c255[3 + c] += (b == 255u) ? cnt2 : 0u;
                    if (b - 1u < 254u) atomicAdd(&sh[(3 + c) * NB + b], cnt2);
                }
            }
        }
    }

    // fold register counters into shared (warp-reduced first: 6 REDs per warp each)
    int lane = threadIdx.x & 31;
    #pragma unroll
    for (int h = 0; h < 6; h++) {
        unsigned int v0 = warpReduceSumU(c0[h]);
        unsigned int v1 = warpReduceSumU(c255[h]);
        if (lane == 0) {
            if (v0) atomicAdd(&sh[h * NB + 0],   v0);
            if (v1) atomicAdd(&sh[h * NB + 255], v1);
        }
    }
    __syncthreads();

    // single flush per block: evenly spread REDs over the 1536 hist words
    for (int i = threadIdx.x; i < 6 * NB; i += blockDim.x) {
        unsigned int v = sh[i];
        if (v) atomicAdd(&g_hist[i], v);
    }

    // ---- last-block fused tables ----
    __shared__ bool s_last;
    __threadfence();
    if (threadIdx.x == 0) {
        unsigned int ticket = atomicAdd(&g_done_hist, 1u);
        s_last = (ticket == gridDim.x - 1);
        if (s_last) g_done_hist = 0u;   // reset for next replay
    }
    __syncthreads();
    if (!s_last) return;

    __shared__ unsigned int s0[NB], s1[NB];
    __shared__ float r[3][NB];   // cdf_dst
    __shared__ float a[3][NB];   // cdf_ref
    int i = threadIdx.x;

    for (int h = 0; h < 6; h++) {
        s0[i] = g_hist[h * NB + i];
        __syncthreads();
        unsigned int* src = s0; unsigned int* dst = s1;
        #pragma unroll
        for (int off = 1; off < NB; off <<= 1) {   // Hillis-Steele, exact integer adds
            unsigned int v = src[i];
            if (i >= off) v += src[i - off];
            dst[i] = v;
            __syncthreads();
            unsigned int* tmpp = src; src = dst; dst = tmpp;
        }
        float tot = (float)src[NB - 1];
        float v = (float)src[i] / tot;             // matches jnp: exact int in f32, then divide
        if (h < 3) r[h][i] = v; else a[h - 3][i] = v;
        __syncthreads();
    }

    #pragma unroll
    for (int c = 0; c < 3; c++) {
        float tbl;
        if (i == 0)           tbl = 0.0f;
        else if (i == NB - 1) tbl = 255.0f;
        else {
            float ri = r[c][i];
            int j = -1;
            for (int jj = 1; jj < NB; jj++) {
                if (ri >= a[c][jj - 1] && ri <= a[c][jj]) { j = jj; break; }
            }
            tbl = (j >= 0) ? (float)j : (float)i;
        }
        g_table[c * NB + i] = tbl;
    }
}

// ---------------- K4: loss over all pixels (pure-read stream) + fused finalize ----------------
__global__ void __launch_bounds__(256) k_loss(
    const float* __restrict__ inp, const float* __restrict__ ref,
    const float* __restrict__ msrc, float* __restrict__ out)
{
    __shared__ float stab[3 * NB];
    for (int i = threadIdx.x; i < 3 * NB; i += blockDim.x) stab[i] = g_table[i];
    __syncthreads();

    const float4* m4  = reinterpret_cast<const float4*>(msrc);
    const float4* in4 = reinterpret_cast<const float4*>(inp);
    const float4* rf4 = reinterpret_cast<const float4*>(ref);
    const uint4*  b4  = reinterpret_cast<const uint4*>(g_bin_ref);

    float acc = 0.0f;
    int stride = gridDim.x * blockDim.x;
    const int NP4 = HH / 4;
    for (int idx = blockIdx.x * blockDim.x + threadIdx.x; idx < NP4; idx += stride) {
        float4 ms = m4[idx];
        uint4  bw = b4[idx];
        float msA[4] = {ms.x, ms.y, ms.z, ms.w};
        unsigned int wA[4] = {bw.x, bw.y, bw.z, bw.w};
        #pragma unroll
        for (int c = 0; c < 3; c++) {
            float4 iv = in4[c * NP4 + idx];
            float4 rv = rf4[c * NP4 + idx];
            float ivA[4] = {iv.x, iv.y, iv.z, iv.w};
            float rvA[4] = {rv.x, rv.y, rv.z, rv.w};
            #pragma unroll
            for (int l = 0; l < 4; l++) {
                float im = dn255(ivA[l]) * msA[l];
                float rm = dn255(rvA[l]) * msA[l];
                float match = (wA[l] >> CNT_SHIFT)
                            ? stab[c * NB + (int)((wA[l] >> (8 * c)) & 255u)]
                            : rm;
                acc += fabsf(im - match);
            }
        }
    }

    // block reduce -> double atomic; last block finalizes
    float s = warpReduceSumF(acc);
    __shared__ float ws[32];
    int lane = threadIdx.x & 31, w = threadIdx.x >> 5;
    if (lane == 0) ws[w] = s;
    __syncthreads();
    if (w == 0) {
        float v = (lane < (int)(blockDim.x >> 5)) ? ws[lane] : 0.0f;
        v = warpReduceSumF(v);
        if (lane == 0) {
            atomicAdd(&g_acc, (double)v);
            __threadfence();
            unsigned int ticket = atomicAdd(&g_done_loss, 1u);
            if (ticket == gridDim.x - 1) {
                out[0] = (float)(g_acc / (double)(3.0 * (double)HH));
                g_done_loss = 0u;   // reset for next replay
            }
        }
    }
}

// ---------------- launch ----------------
extern "C" void kernel_launch(void* const* d_in, const int* in_sizes, int n_in,
                              void* d_out, int out_size)
{
    const float* input_data  = (const float*)d_in[0];
    const float* target_data = (const float*)d_in[1];
    const float* ref         = (const float*)d_in[2];
    const float* mask_src    = (const float*)d_in[3];
    const float* mask_tar    = (const float*)d_in[4];
    const int* idx0 = (const int*)d_in[5];
    const int* idx1 = (const int*)d_in[6];
    const int* idx2 = (const int*)d_in[7];
    const int* idx3 = (const int*)d_in[8];
    float* out = (float*)d_out;

    k_binify<<<HH / 4 / 256, 256>>>(ref, target_data, mask_src, mask_tar);
    k_sample<<<(NIDX / SPT + 255) / 256, 256>>>(idx0, idx1, idx2, idx3);
    k_hist<<<512, 256>>>();
    k_loss<<<2048, 256>>>(input_data, ref, mask_src, out);
}